// round 5
// baseline (speedup 1.0000x reference)
#include <cuda_runtime.h>
#include <cuda_fp16.h>
#include <math.h>

// GreenTF as an exponentially-windowed complex IIR filter bank.
//   z[n]   = sum_{m>=0} wav[n-m] * alpha^m,  alpha = 2^(-1/320) * cis(2*pi*f/16000)
//   S[f,t] = z[16t] - alpha^2048 * z[16(t-128)]       (exact truncation correction)
// t-chunked (5 x 400 outputs) with 128-step exact warm-up (2048 = 16*128 makes
// the ring difference cancel missing pre-history exactly). 630 CTAs = single
// wave at 5 CTAs/SM (occupancy push: fp8 ring = 32KB/CTA, <=102 regs).
// Ring r[t-128] in shared memory as e4m3x2; correction weight 0.0118 bounds
// fp8 rounding to ~1e-4 aggregate. r globally scaled x16 for e4m3 range.

#define NFREQ   8001
#define NCHAIN  (2 * NFREQ)
#define TOUT    2000
#define TWAV    32000
#define SR_I    16000
#define CHUNK   400
#define NCHUNK  5
#define WARM    128
#define BLOCK   128

static __device__ __forceinline__ unsigned long long pk2(float x, float y) {
    unsigned long long r;
    asm("mov.b64 %0, {%1,%2};" : "=l"(r) : "f"(x), "f"(y));
    return r;
}
static __device__ __forceinline__ float2 upk2(unsigned long long v) {
    float2 r;
    asm("mov.b64 {%0,%1}, %2;" : "=f"(r.x), "=f"(r.y) : "l"(v));
    return r;
}
static __device__ __forceinline__ unsigned long long ffma2_(
    unsigned long long a, unsigned long long b, unsigned long long c) {
    unsigned long long d;
    asm("fma.rn.f32x2 %0, %1, %2, %3;" : "=l"(d) : "l"(a), "l"(b), "l"(c));
    return d;
}
static __device__ __forceinline__ unsigned long long fmul2_(
    unsigned long long a, unsigned long long b) {
    unsigned long long d;
    asm("mul.rn.f32x2 %0, %1, %2;" : "=l"(d) : "l"(a), "l"(b));
    return d;
}
// float2 -> packed e4m3x2 (hi = y, lo = x)
static __device__ __forceinline__ unsigned short f2_to_e4m3x2(float x, float y) {
    unsigned short u;
    asm("cvt.rn.satfinite.e4m3x2.f32 %0, %1, %2;" : "=h"(u) : "f"(y), "f"(x));
    return u;
}
// packed e4m3x2 -> float2
static __device__ __forceinline__ float2 e4m3x2_to_f2(unsigned short u) {
    unsigned int h2;
    asm("cvt.rn.f16x2.e4m3x2 %0, %1;" : "=r"(h2) : "h"(u));
    __half2 h = *reinterpret_cast<__half2*>(&h2);
    return __half22float2(h);
}

extern __shared__ unsigned short s_ring[];   // [WARM][BLOCK] e4m3x2 : 32 KB

__global__ void __launch_bounds__(BLOCK, 5)
greentf_kernel(const float* __restrict__ wav, float* __restrict__ out)
{
    const int tid = threadIdx.x;
    int gid = blockIdx.x * BLOCK + tid;
    if (gid >= NCHAIN) return;
    const int chunk = blockIdx.y;
    const int b = gid / NFREQ;
    const int f = gid - b * NFREQ;
    const float* __restrict__ w = wav + b * TWAV;

    const float TW = 6.283185307179586f / 16000.0f;
    const float RS = 16.0f, invRS = 0.0625f;

    // SC = sqrt(8) / sum_{m=0}^{2047} rho^m ; fold x16 (fp8 range) into it
    double rho = exp2(-1.0 / 320.0);
    double geo = (1.0 - exp2(-2048.0 / 320.0)) / (1.0 - rho);
    const float SCg = (float)(2.8284271247461903 / geo) * RS;

    // d_j = SCg * alpha^{-j}, j=1..15 (slot 0 zeroed; cur[0] enters directly)
    float djr[16], dji[16];
    djr[0] = 0.f; dji[0] = 0.f;
#pragma unroll
    for (int j = 1; j < 16; ++j) {
        int ph = (f * j) % SR_I;
        float s, c;
        sincosf(TW * (float)ph, &s, &c);
        float g = SCg * exp2f((float)j * (1.0f / 320.0f));
        djr[j] = c * g;
        dji[j] = -s * g;
    }
    unsigned long long dR2[8], dI2[8];
#pragma unroll
    for (int p = 0; p < 8; ++p) {
        dR2[p] = pk2(djr[2 * p], djr[2 * p + 1]);
        dI2[p] = pk2(dji[2 * p], dji[2 * p + 1]);
    }

    float A16r, A16i;
    {
        int ph = (16 * f) % SR_I;
        float s, c;
        sincosf(TW * (float)ph, &s, &c);
        float d = exp2f(-16.0f / 320.0f);
        A16r = c * d; A16i = s * d;
    }
    float A2r, A2i;
    {
        int ph = (2048 * f) % SR_I;
        float s, c;
        sincosf(TW * (float)ph, &s, &c);
        float d = exp2f(-2048.0f / 320.0f);
        A2r = c * d; A2i = s * d;
    }

    float rr = 0.f, ri = 0.f, Gr = 0.f, Gi = 0.f;   // scaled by SCg
    const int t0 = chunk * CHUNK;

    if (chunk == 0) {
#pragma unroll 8
        for (int i = 0; i < WARM; ++i) s_ring[i * BLOCK + tid] = 0;
    } else {
        for (int t = t0 - WARM; t < t0; ++t) {
            const ulonglong2* p = (const ulonglong2*)(w + 16 * t);
            ulonglong2 u0 = p[0], u1 = p[1], u2 = p[2], u3 = p[3];
            unsigned long long c2[8] = { u0.x, u0.y, u1.x, u1.y,
                                         u2.x, u2.y, u3.x, u3.y };
            float cur0s = upk2(c2[0]).x * SCg;
            float tr = rr + Gr, ti = ri + Gi;
            rr = fmaf(A16r, tr, fmaf(-A16i, ti, cur0s));
            ri = fmaf(A16i, tr, A16r * ti);
            unsigned long long aR = fmul2_(c2[0], dR2[0]);
            unsigned long long aI = fmul2_(c2[0], dI2[0]);
#pragma unroll
            for (int q = 1; q < 8; ++q) {
                aR = ffma2_(c2[q], dR2[q], aR);
                aI = ffma2_(c2[q], dI2[q], aI);
            }
            float2 ar = upk2(aR), ai = upk2(aI);
            Gr = ar.x + ar.y;
            Gi = ai.x + ai.y;
            s_ring[(t & (WARM - 1)) * BLOCK + tid] = f2_to_e4m3x2(rr, ri);
        }
    }

    float* __restrict__ outs = out + (size_t)gid * TOUT + t0;
    float* __restrict__ outc = out + (size_t)NCHAIN * TOUT + (size_t)gid * TOUT + t0;

    for (int q0 = 0; q0 < CHUNK; q0 += 4) {
        float obs[4], obc[4];
#pragma unroll
        for (int half = 0; half < 2; ++half) {
            const int tb = t0 + q0 + 2 * half;

            // batched prefetch: 2 ring reads + 8 wav LDG.128
            unsigned short hraw[2];
#pragma unroll
            for (int u = 0; u < 2; ++u)
                hraw[u] = s_ring[((tb + u) & (WARM - 1)) * BLOCK + tid];
            ulonglong2 U[2][4];
#pragma unroll
            for (int u = 0; u < 2; ++u) {
                const ulonglong2* p = (const ulonglong2*)(w + 16 * (tb + u));
#pragma unroll
                for (int k = 0; k < 4; ++k) U[u][k] = p[k];
            }

#pragma unroll
            for (int u = 0; u < 2; ++u) {
                unsigned long long c2[8] = { U[u][0].x, U[u][0].y, U[u][1].x, U[u][1].y,
                                             U[u][2].x, U[u][2].y, U[u][3].x, U[u][3].y };
                float cur0s = upk2(c2[0]).x * SCg;
                float tr = rr + Gr, ti = ri + Gi;
                rr = fmaf(A16r, tr, fmaf(-A16i, ti, cur0s));
                ri = fmaf(A16i, tr, A16r * ti);
                unsigned long long aR = fmul2_(c2[0], dR2[0]);
                unsigned long long aI = fmul2_(c2[0], dI2[0]);
#pragma unroll
                for (int q = 1; q < 8; ++q) {
                    aR = ffma2_(c2[q], dR2[q], aR);
                    aI = ffma2_(c2[q], dI2[q], aI);
                }
                float2 ar = upk2(aR), ai = upk2(aI);
                Gr = ar.x + ar.y;
                Gi = ai.x + ai.y;

                // S = r - alpha^2048 * r[t-128]
                float2 h = e4m3x2_to_f2(hraw[u]);
                s_ring[((tb + u) & (WARM - 1)) * BLOCK + tid] = f2_to_e4m3x2(rr, ri);
                float Sr = fmaf(-A2r, h.x, fmaf( A2i, h.y, rr));
                float Si = fmaf(-A2i, h.x, fmaf(-A2r, h.y, ri));
                obs[2 * half + u] = Si * invRS;
                obc[2 * half + u] = Sr * invRS;
            }
        }
        *(float4*)(outs + q0) = make_float4(obs[0], obs[1], obs[2], obs[3]);
        *(float4*)(outc + q0) = make_float4(obc[0], obc[1], obc[2], obc[3]);
    }
}

extern "C" void kernel_launch(void* const* d_in, const int* in_sizes, int n_in,
                              void* d_out, int out_size)
{
    (void)in_sizes; (void)n_in; (void)out_size;
    const float* wav = (const float*)d_in[0];   // (2, 32000) fp32
    float* out = (float*)d_out;                 // sspec then cspec, fp32

    static const int smem_bytes = WARM * BLOCK * (int)sizeof(unsigned short); // 32 KB
    cudaFuncSetAttribute(greentf_kernel,
                         cudaFuncAttributeMaxDynamicSharedMemorySize, smem_bytes);

    dim3 grid((NCHAIN + BLOCK - 1) / BLOCK, NCHUNK, 1);   // 126 x 5 = 630 CTAs
    greentf_kernel<<<grid, BLOCK, smem_bytes>>>(wav, out);
}